// round 13
// baseline (speedup 1.0000x reference)
#include <cuda_runtime.h>

#define HID   64
#define RS    8
#define KIH   24
#define WIDTH 24
#define L0R   8
#define R0R   24
#define OW    16
#define PB    8          // batches per warp-pair
#define NPAIR 4
#define NTHR  256
#define CTAB  32
#define RBW   24

// smem float offsets
#define OFF_W    0
#define W_FLOATS (4*44*32*4)                 // 22528: [gate g][kp][lane] quads
#define OFF_BIAS (OFF_W + W_FLOATS)          // 22528
#define OFF_WL   (OFF_BIAS + 256)            // 22784
#define OFF_BL   (OFF_WL + 192)              // 22976
#define OFF_HX   (OFF_BL + 4)                // 22980 (x4 -> 16B aligned)
#define HXBUF    (NPAIR*PB*HID)              // 2048 per buffer
#define OFF_XCH  (OFF_HX + 2*HXBUF)          // 27076 (x4 -> 8B aligned)
#define XCH_FLOATS (NPAIR*2*4*2*32*2)        // 4096
#define OFF_RBQ  (OFF_XCH + XCH_FLOATS)      // 31172 (x4 -> 16B aligned)
#define RBQ_FLOATS (NPAIR*PB*3*RBW*4)        // 9216
#define SMEM_FLOATS (OFF_RBQ + RBQ_FLOATS)   // 40388 -> ~162 KB

typedef unsigned long long u64;

union F4U { float4 f4; struct { u64 lo, hi; } u; };
union F2U { float2 f2; u64 u; };

static __device__ __forceinline__ u64 pack2(float a, float b){
  u64 r; asm("mov.b64 %0, {%1, %2};" : "=l"(r) : "f"(a), "f"(b)); return r;
}
static __device__ __forceinline__ void unpack2(u64 v, float& a, float& b){
  asm("mov.b64 {%0, %1}, %2;" : "=f"(a), "=f"(b) : "l"(v));
}
static __device__ __forceinline__ u64 ffma2(u64 a, u64 b, u64 c){
  u64 d; asm("fma.rn.f32x2 %0, %1, %2, %3;" : "=l"(d) : "l"(a), "l"(b), "l"(c));
  return d;
}
static __device__ __forceinline__ float tanha(float x){
  float y; asm("tanh.approx.f32 %0, %1;" : "=f"(y) : "f"(x)); return y;
}
static __device__ __forceinline__ float sigf(float x){
  return fmaf(tanha(0.5f*x), 0.5f, 0.5f);
}

#define PBAR() asm volatile("bar.sync %0, 64;" :: "r"(pair + 1) : "memory")

__global__ void __launch_bounds__(NTHR, 1)
pixelrnn_kernel(const float* __restrict__ x,
                const float* __restrict__ W_ih,
                const float* __restrict__ W_hh,
                const float* __restrict__ b_ih,
                const float* __restrict__ b_hh,
                const float* __restrict__ Wl,
                const float* __restrict__ bl,
                float* __restrict__ out)
{
  extern __shared__ float sm[];
  const int tid  = threadIdx.x;
  const int warp = tid >> 5, lane = tid & 31;
  const int pair = warp >> 1, half = warp & 1;

  // ---- stage weights ----
  // W4[(g*44 + kp)*32 + ln] =
  //   ( w(2kp, g*64+ln), w(2kp+1, g*64+ln), w(2kp, g*64+ln+32), w(2kp+1, g*64+ln+32) )
  //   u.lo = (k0,k1) for hidA row; u.hi = (k0,k1) for hidB row
  //   k < 24 -> W_ih col k; else W_hh col k-24.  g = 0:i 1:f 2:g 3:o
  {
    float4* W4 = (float4*)(sm + OFF_W);
    for (int i = tid; i < 4*44*32; i += NTHR){
      int ln = i & 31;
      int kp = (i >> 5) % 44;
      int g  = i / (44*32);
      int rA = g*64 + ln, rB = rA + 32;
      int k0 = 2*kp;
      float4 v;
      if (k0 < KIH){
        v = make_float4(W_ih[rA*KIH + k0], W_ih[rA*KIH + k0 + 1],
                        W_ih[rB*KIH + k0], W_ih[rB*KIH + k0 + 1]);
      } else {
        int kk = k0 - KIH;
        v = make_float4(W_hh[rA*HID + kk], W_hh[rA*HID + kk + 1],
                        W_hh[rB*HID + kk], W_hh[rB*HID + kk + 1]);
      }
      W4[i] = v;
    }
  }
  for (int i = tid; i < 256; i += NTHR) sm[OFF_BIAS + i] = b_ih[i] + b_hh[i];
  for (int i = tid; i < 3*HID; i += NTHR) sm[OFF_WL + i] = Wl[i];
  if (tid < 3) sm[OFF_BL + tid] = bl[tid];
  for (int i = tid; i < 2*HXBUF; i += NTHR) sm[OFF_HX + i] = 0.f;
  __syncthreads();

  const int bpair = blockIdx.x * CTAB + pair * PB;
  float* hxb0 = sm + OFF_HX + pair * (PB*HID);
  float* hxb1 = hxb0 + HXBUF;
  // exchange region: per pair 512 float2 (2 writer-halves x 4 pb x 2 tt x 32)
  F2U* xchw = (F2U*)(sm + OFF_XCH) + pair*512 + half*256;
  F2U* xchr = (F2U*)(sm + OFF_XCH) + pair*512 + (1 - half)*256;
  float4* rbq = (float4*)(sm + OFF_RBQ) + pair * (PB*3*RBW);
  float*  rbf = (float*)rbq;
  // this warp's 2 gate types: g = half*2 + tt
  const float4* wq  = (const float4*)(sm + OFF_W) + (half*2)*(44*32) + lane;
  const float4* wlq = (const float4*)(sm + OFF_WL);

  u64 bj[2][2];
#pragma unroll
  for (int t = 0; t < 2; t++)
#pragma unroll
    for (int h = 0; h < 2; h++)
      bj[t][h] = pack2(sm[OFF_BIAS + (half*2 + t)*64 + lane + 32*h], 0.f);

  // owned batches: half0 -> 0..3, half1 -> 4..7
  float cxA[4], cxB[4];
#pragma unroll
  for (int bb = 0; bb < 4; bb++){ cxA[bb] = 0.f; cxB[bb] = 0.f; }

  const int  vb = lane / 3, vch = lane - 3*vb;     // lanes 0..11
  const bool vact = (lane < 12);
  const int  vabs = half*4 + vb;
  const float blv = vact ? sm[OFF_BL + vch] : 0.f;
  float* outq = vact ? out + ((size_t)(bpair + vabs)*3 + vch)*(OW*OW) : out;

  int ph = 0, sctr = 0;

  for (int r = L0R; r < R0R; r++){
    // init slots 0..7 from x (cols >= 8 get v-patched before any read)
    for (int i = half*32 + lane; i < PB*3*8; i += 64){
      int b = i / 24;
      int rem = i - b*24;
      int ch = rem >> 3, s = rem & 7;
      const float* xr = x + (size_t)(bpair + b)*(3*WIDTH*WIDTH)
                          + ch*(WIDTH*WIDTH) + r*WIDTH + s;
      rbq[(b*3 + ch)*RBW + s] = make_float4(xr[0], xr[1], xr[2], xr[3]);
    }
    PBAR();

    for (int c = RS; c < WIDTH; c++){
      float* hxr = ph ? hxb1 : hxb0;   // h(t-1)
      float* hxw = ph ? hxb0 : hxb1;   // h(t)
      const float4* hxq = (const float4*)hxr;

      // acc[b][tt][h]: u64 = (even-k partial, odd-k partial)
      u64 acc[PB][2][2];
#pragma unroll
      for (int b = 0; b < PB; b++)
#pragma unroll
        for (int t = 0; t < 2; t++){
          acc[b][t][0] = bj[t][0];
          acc[b][t][1] = bj[t][1];
        }

      // ---- input feed: 6 quads (iq -> ch=iq>>1, kp = 2iq, 2iq+1) ----
#pragma unroll
      for (int iq = 0; iq < 6; iq++){
        F4U w00, w01, w10, w11;
        w00.f4 = wq[(0*44 + 2*iq + 0)*32];
        w01.f4 = wq[(0*44 + 2*iq + 1)*32];
        w10.f4 = wq[(1*44 + 2*iq + 0)*32];
        w11.f4 = wq[(1*44 + 2*iq + 1)*32];
        int ch = iq >> 1;
        int base = c - RS + 4*(iq & 1);
#pragma unroll
        for (int b = 0; b < PB; b++){
          F4U a; a.f4 = rbq[(b*3 + ch)*RBW + base];
          acc[b][0][0] = ffma2(a.u.lo, w00.u.lo, acc[b][0][0]);
          acc[b][0][1] = ffma2(a.u.lo, w00.u.hi, acc[b][0][1]);
          acc[b][1][0] = ffma2(a.u.lo, w10.u.lo, acc[b][1][0]);
          acc[b][1][1] = ffma2(a.u.lo, w10.u.hi, acc[b][1][1]);
          acc[b][0][0] = ffma2(a.u.hi, w01.u.lo, acc[b][0][0]);
          acc[b][0][1] = ffma2(a.u.hi, w01.u.hi, acc[b][0][1]);
          acc[b][1][0] = ffma2(a.u.hi, w11.u.lo, acc[b][1][0]);
          acc[b][1][1] = ffma2(a.u.hi, w11.u.hi, acc[b][1][1]);
        }
      }

      // ---- hidden feed: 16 quads (jq -> kp = 12+2jq, 13+2jq) ----
#pragma unroll 4
      for (int jq = 0; jq < 16; jq++){
        F4U w00, w01, w10, w11;
        w00.f4 = wq[(0*44 + 12 + 2*jq + 0)*32];
        w01.f4 = wq[(0*44 + 12 + 2*jq + 1)*32];
        w10.f4 = wq[(1*44 + 12 + 2*jq + 0)*32];
        w11.f4 = wq[(1*44 + 12 + 2*jq + 1)*32];
#pragma unroll
        for (int b = 0; b < PB; b++){
          F4U a; a.f4 = hxq[b*16 + jq];
          acc[b][0][0] = ffma2(a.u.lo, w00.u.lo, acc[b][0][0]);
          acc[b][0][1] = ffma2(a.u.lo, w00.u.hi, acc[b][0][1]);
          acc[b][1][0] = ffma2(a.u.lo, w10.u.lo, acc[b][1][0]);
          acc[b][1][1] = ffma2(a.u.lo, w10.u.hi, acc[b][1][1]);
          acc[b][0][0] = ffma2(a.u.hi, w01.u.lo, acc[b][0][0]);
          acc[b][0][1] = ffma2(a.u.hi, w01.u.hi, acc[b][0][1]);
          acc[b][1][0] = ffma2(a.u.hi, w11.u.lo, acc[b][1][0]);
          acc[b][1][1] = ffma2(a.u.hi, w11.u.hi, acc[b][1][1]);
        }
      }

      // ---- finalize: export partner's batches, keep own ----
      // partner batches: half0 exports b4..7 (pb=b-4); half1 exports b0..3 (pb=b)
#pragma unroll
      for (int pb = 0; pb < 4; pb++){
        int b = pb + (half ? 0 : 4);
#pragma unroll
        for (int t = 0; t < 2; t++){
          float eA, oA, eB, oB;
          unpack2(acc[b][t][0], eA, oA);
          unpack2(acc[b][t][1], eB, oB);
          F2U v; v.f2 = make_float2(eA + oA, eB + oB);
          xchw[(pb*2 + t)*32 + lane] = v;
        }
      }
      float mA[4][2], mB[4][2];   // own gates: [bb][tt] for hidA/hidB
#pragma unroll
      for (int bb = 0; bb < 4; bb++){
        int b = bb + half*4;
#pragma unroll
        for (int t = 0; t < 2; t++){
          float eA, oA, eB, oB;
          unpack2(acc[b][t][0], eA, oA);
          unpack2(acc[b][t][1], eB, oB);
          mA[bb][t] = eA + oA;
          mB[bb][t] = eB + oB;
        }
      }
      PBAR();   // gate exchange visible

      // ---- cell update for owned batches ----
#pragma unroll
      for (int bb = 0; bb < 4; bb++){
        int b = bb + half*4;
        float2 g0 = xchr[(bb*2 + 0)*32 + lane].f2;   // partner tt0 (A,B)
        float2 g1 = xchr[(bb*2 + 1)*32 + lane].f2;   // partner tt1 (A,B)
        float iA, fA, gA, oA, iB, fB, gB, oB;
        if (half == 0){           // mine = i,f ; partner = g,o
          iA = mA[bb][0]; fA = mA[bb][1]; gA = g0.x; oA = g1.x;
          iB = mB[bb][0]; fB = mB[bb][1]; gB = g0.y; oB = g1.y;
        } else {                  // mine = g,o ; partner = i,f
          gA = mA[bb][0]; oA = mA[bb][1]; iA = g0.x; fA = g1.x;
          gB = mB[bb][0]; oB = mB[bb][1]; iB = g0.y; fB = g1.y;
        }
        float c0 = sigf(fA)*cxA[bb] + sigf(iA)*tanha(gA);
        float c1 = sigf(fB)*cxB[bb] + sigf(iB)*tanha(gB);
        cxA[bb] = c0; cxB[bb] = c1;
        hxw[b*HID + lane]      = sigf(oA)*tanha(c0);
        hxw[b*HID + lane + 32] = sigf(oB)*tanha(c1);
      }
      __syncwarp();

      // ---- head v for owned batches (lanes 0..11) ----
      if (vact){
        const float4* hq = (const float4*)hxw;
        u64 va = pack2(0.f, 0.f);
#pragma unroll
        for (int j = 0; j < 16; j++){
          F4U a; a.f4 = hq[vabs*16 + j];
          F4U w; w.f4 = wlq[vch*16 + j];
          va = ffma2(a.u.lo, w.u.lo, va);
          va = ffma2(a.u.hi, w.u.hi, va);
        }
        float v0, v1; unpack2(va, v0, v1);
        float v = v0 + v1 + blv;
        v = fmaxf(v, 0.01f*v);
#pragma unroll
        for (int t = 0; t < 4; t++)
          rbf[((vabs*3 + vch)*RBW + (c - t))*4 + t] = v;
        outq[sctr] = v;
      }
      PBAR();   // partner hx + v patches visible for next step
      ph ^= 1;
      sctr++;
    }
  }
}

extern "C" void kernel_launch(void* const* d_in, const int* in_sizes, int n_in,
                              void* d_out, int out_size)
{
  const float* x    = (const float*)d_in[0];
  const float* W_ih = (const float*)d_in[1];
  const float* W_hh = (const float*)d_in[2];
  const float* b_ih = (const float*)d_in[3];
  const float* b_hh = (const float*)d_in[4];
  const float* Wl   = (const float*)d_in[5];
  const float* bl   = (const float*)d_in[6];

  int B = in_sizes[0] / (3*WIDTH*WIDTH);
  int grid = B / CTAB;   // 4096/32 = 128 CTAs

  size_t smem = SMEM_FLOATS * sizeof(float);   // ~162 KB
  cudaFuncSetAttribute(pixelrnn_kernel,
                       cudaFuncAttributeMaxDynamicSharedMemorySize, (int)smem);

  pixelrnn_kernel<<<grid, NTHR, smem>>>(x, W_ih, W_hh, b_ih, b_hh, Wl, bl,
                                        (float*)d_out);
}

// round 14
// speedup vs baseline: 1.3493x; 1.3493x over previous
#include <cuda_runtime.h>

#define HID   64
#define RS    8
#define KIH   24
#define WIDTH 24
#define L0R   8
#define R0R   24
#define OW    16
#define WB    4          // batches per warp (warp fully owns them)
#define NWARP 8
#define NTHR  256
#define CTAB  32
#define RBW   25         // padded row stride in quads (bank stagger)

// smem float offsets
#define OFF_W    0
#define W_FLOATS (4*44*32*4)                 // 22528: [gate][kp][lane] quads
#define OFF_BIAS (OFF_W + W_FLOATS)          // 22528
#define OFF_WL   (OFF_BIAS + 256)            // 22784
#define OFF_BL   (OFF_WL + 192)              // 22976
#define OFF_HX   (OFF_BL + 4)                // 22980 (x4 -> 16B aligned)
#define HXBUF    (NWARP*WB*HID)              // 2048 per buffer
#define OFF_RBQ  (OFF_HX + 2*HXBUF)          // 27076 (x4 -> 16B aligned)
#define RBQ_FLOATS (NWARP*WB*3*RBW*4)        // 9600
#define SMEM_FLOATS (OFF_RBQ + RBQ_FLOATS)   // 36676 -> ~147 KB

typedef unsigned long long u64;

union F4U { float4 f4; struct { u64 lo, hi; } u; };

static __device__ __forceinline__ u64 pack2(float a, float b){
  u64 r; asm("mov.b64 %0, {%1, %2};" : "=l"(r) : "f"(a), "f"(b)); return r;
}
static __device__ __forceinline__ void unpack2(u64 v, float& a, float& b){
  asm("mov.b64 {%0, %1}, %2;" : "=f"(a), "=f"(b) : "l"(v));
}
static __device__ __forceinline__ u64 ffma2(u64 a, u64 b, u64 c){
  u64 d; asm("fma.rn.f32x2 %0, %1, %2, %3;" : "=l"(d) : "l"(a), "l"(b), "l"(c));
  return d;
}
static __device__ __forceinline__ float tanha(float x){
  float y; asm("tanh.approx.f32 %0, %1;" : "=f"(y) : "f"(x)); return y;
}
static __device__ __forceinline__ float sigf(float x){
  return fmaf(tanha(0.5f*x), 0.5f, 0.5f);
}

__global__ void __launch_bounds__(NTHR, 1)
pixelrnn_kernel(const float* __restrict__ x,
                const float* __restrict__ W_ih,
                const float* __restrict__ W_hh,
                const float* __restrict__ b_ih,
                const float* __restrict__ b_hh,
                const float* __restrict__ Wl,
                const float* __restrict__ bl,
                float* __restrict__ out)
{
  extern __shared__ float sm[];
  const int tid  = threadIdx.x;
  const int warp = tid >> 5, lane = tid & 31;

  // ---- stage weights (shared by all warps) ----
  // W4[(g*44 + kp)*32 + ln] =
  //   ( w(2kp, g*64+ln), w(2kp+1, g*64+ln), w(2kp, g*64+ln+32), w(2kp+1, g*64+ln+32) )
  //   u.lo = (k0,k1) for hidA row; u.hi = (k0,k1) for hidB row
  //   k < 24 -> W_ih col k; else W_hh col k-24.  g = 0:i 1:f 2:g 3:o
  {
    float4* W4 = (float4*)(sm + OFF_W);
    for (int i = tid; i < 4*44*32; i += NTHR){
      int ln = i & 31;
      int kp = (i >> 5) % 44;
      int g  = i / (44*32);
      int rA = g*64 + ln, rB = rA + 32;
      int k0 = 2*kp;
      float4 v;
      if (k0 < KIH){
        v = make_float4(W_ih[rA*KIH + k0], W_ih[rA*KIH + k0 + 1],
                        W_ih[rB*KIH + k0], W_ih[rB*KIH + k0 + 1]);
      } else {
        int kk = k0 - KIH;
        v = make_float4(W_hh[rA*HID + kk], W_hh[rA*HID + kk + 1],
                        W_hh[rB*HID + kk], W_hh[rB*HID + kk + 1]);
      }
      W4[i] = v;
    }
  }
  for (int i = tid; i < 256; i += NTHR) sm[OFF_BIAS + i] = b_ih[i] + b_hh[i];
  for (int i = tid; i < 3*HID; i += NTHR) sm[OFF_WL + i] = Wl[i];
  if (tid < 3) sm[OFF_BL + tid] = bl[tid];
  for (int i = tid; i < 2*HXBUF; i += NTHR) sm[OFF_HX + i] = 0.f;
  __syncthreads();

  const int bbase = blockIdx.x * CTAB + warp * WB;
  float* hxb0 = sm + OFF_HX + warp * (WB*HID);
  float* hxb1 = hxb0 + HXBUF;
  float4* rbq = (float4*)(sm + OFF_RBQ) + warp * (WB*3*RBW);
  float*  rbf = (float*)rbq;
  const float4* wq  = (const float4*)(sm + OFF_W) + lane;
  const float4* wlq = (const float4*)(sm + OFF_WL);

  // biases: acc[b][g][h] starts as (bias, 0) since (even,odd) partials
  u64 bj[4][2];
#pragma unroll
  for (int g = 0; g < 4; g++){
    bj[g][0] = pack2(sm[OFF_BIAS + g*64 + lane],      0.f);
    bj[g][1] = pack2(sm[OFF_BIAS + g*64 + lane + 32], 0.f);
  }

  float cx0[WB], cx1[WB];
#pragma unroll
  for (int b = 0; b < WB; b++){ cx0[b] = 0.f; cx1[b] = 0.f; }

  // v-head: 2 lanes per (vb,vch) dot. pairid = lane>>1 in 0..11
  const int  pid = lane >> 1, sub = lane & 1;
  const int  vb = pid / 3, vch = pid - 3*vb;
  const bool vact = (lane < 24);
  const float blv = vact ? sm[OFF_BL + vch] : 0.f;
  float* outq = vact ? out + ((size_t)(bbase + vb)*3 + vch)*(OW*OW) : out;

  int ph = 0, sctr = 0;

  for (int r = L0R; r < R0R; r++){
    // init slots 0..7 from x (cols >= 8 get v-patched before any read)
    for (int i = lane; i < WB*3*8; i += 32){
      int b = i / 24;
      int rem = i - b*24;
      int ch = rem >> 3, s = rem & 7;
      const float* xr = x + (size_t)(bbase + b)*(3*WIDTH*WIDTH)
                          + ch*(WIDTH*WIDTH) + r*WIDTH + s;
      rbq[(b*3 + ch)*RBW + s] = make_float4(xr[0], xr[1], xr[2], xr[3]);
    }
    __syncwarp();

    for (int c = RS; c < WIDTH; c++){
      float* hxr = ph ? hxb1 : hxb0;   // h(t-1)
      float* hxw = ph ? hxb0 : hxb1;   // h(t)
      const float4* hxq = (const float4*)hxr;

      // acc[b][g][h]: u64 = (even-k partial, odd-k partial), h: 0=hidA 1=hidB
      u64 acc[WB][4][2];
#pragma unroll
      for (int b = 0; b < WB; b++)
#pragma unroll
        for (int g = 0; g < 4; g++){
          acc[b][g][0] = bj[g][0];
          acc[b][g][1] = bj[g][1];
        }

      // ---- input feed: 6 quads (iq -> ch=iq>>1, kp = 2iq, 2iq+1) ----
#pragma unroll
      for (int iq = 0; iq < 6; iq++){
        F4U w0[4], w1[4];
#pragma unroll
        for (int g = 0; g < 4; g++){
          w0[g].f4 = wq[(g*44 + 2*iq + 0)*32];
          w1[g].f4 = wq[(g*44 + 2*iq + 1)*32];
        }
        int ch = iq >> 1;
        int base = c - RS + 4*(iq & 1);
#pragma unroll
        for (int b = 0; b < WB; b++){
          F4U a; a.f4 = rbq[(b*3 + ch)*RBW + base];
#pragma unroll
          for (int g = 0; g < 4; g++){
            acc[b][g][0] = ffma2(a.u.lo, w0[g].u.lo, acc[b][g][0]);
            acc[b][g][1] = ffma2(a.u.lo, w0[g].u.hi, acc[b][g][1]);
            acc[b][g][0] = ffma2(a.u.hi, w1[g].u.lo, acc[b][g][0]);
            acc[b][g][1] = ffma2(a.u.hi, w1[g].u.hi, acc[b][g][1]);
          }
        }
      }

      // ---- hidden feed: 16 quads (jq -> kp = 12+2jq, 13+2jq) ----
#pragma unroll 8
      for (int jq = 0; jq < 16; jq++){
        F4U w0[4], w1[4];
#pragma unroll
        for (int g = 0; g < 4; g++){
          w0[g].f4 = wq[(g*44 + 12 + 2*jq + 0)*32];
          w1[g].f4 = wq[(g*44 + 12 + 2*jq + 1)*32];
        }
#pragma unroll
        for (int b = 0; b < WB; b++){
          F4U a; a.f4 = hxq[b*16 + jq];
#pragma unroll
          for (int g = 0; g < 4; g++){
            acc[b][g][0] = ffma2(a.u.lo, w0[g].u.lo, acc[b][g][0]);
            acc[b][g][1] = ffma2(a.u.lo, w0[g].u.hi, acc[b][g][1]);
            acc[b][g][0] = ffma2(a.u.hi, w1[g].u.lo, acc[b][g][0]);
            acc[b][g][1] = ffma2(a.u.hi, w1[g].u.hi, acc[b][g][1]);
          }
        }
      }

      // ---- lane-local cell update (sum even/odd streams, then activate) ----
#pragma unroll
      for (int b = 0; b < WB; b++){
        float e, o;
        unpack2(acc[b][0][0], e, o); float giA = e + o;
        unpack2(acc[b][1][0], e, o); float gfA = e + o;
        unpack2(acc[b][2][0], e, o); float ggA = e + o;
        unpack2(acc[b][3][0], e, o); float goA = e + o;
        unpack2(acc[b][0][1], e, o); float giB = e + o;
        unpack2(acc[b][1][1], e, o); float gfB = e + o;
        unpack2(acc[b][2][1], e, o); float ggB = e + o;
        unpack2(acc[b][3][1], e, o); float goB = e + o;
        float c0 = sigf(gfA)*cx0[b] + sigf(giA)*tanha(ggA);
        float c1 = sigf(gfB)*cx1[b] + sigf(giB)*tanha(ggB);
        cx0[b] = c0; cx1[b] = c1;
        hxw[b*HID + lane]      = sigf(goA)*tanha(c0);
        hxw[b*HID + lane + 32] = sigf(goB)*tanha(c1);
      }
      __syncwarp();

      // ---- head v: 2 lanes per dot (lanes 0..23), shfl-combine ----
      float vtot = 0.f;
      if (vact){
        const float4* hq = (const float4*)hxw;
        u64 va = pack2(0.f, 0.f);
#pragma unroll
        for (int j = 0; j < 8; j++){
          F4U a; a.f4 = hq[vb*16 + sub*8 + j];
          F4U w; w.f4 = wlq[vch*16 + sub*8 + j];
          va = ffma2(a.u.lo, w.u.lo, va);
          va = ffma2(a.u.hi, w.u.hi, va);
        }
        float v0, v1; unpack2(va, v0, v1);
        vtot = v0 + v1;
      }
      vtot += __shfl_xor_sync(0xFFFFFFFFu, vtot, 1);
      if (vact && sub == 0){
        float v = vtot + blv;
        v = fmaxf(v, 0.01f*v);
#pragma unroll
        for (int t = 0; t < 4; t++)
          rbf[((vb*3 + vch)*RBW + (c - t))*4 + t] = v;
        outq[sctr] = v;
      }
      __syncwarp();
      ph ^= 1;
      sctr++;
    }
  }
}

extern "C" void kernel_launch(void* const* d_in, const int* in_sizes, int n_in,
                              void* d_out, int out_size)
{
  const float* x    = (const float*)d_in[0];
  const float* W_ih = (const float*)d_in[1];
  const float* W_hh = (const float*)d_in[2];
  const float* b_ih = (const float*)d_in[3];
  const float* b_hh = (const float*)d_in[4];
  const float* Wl   = (const float*)d_in[5];
  const float* bl   = (const float*)d_in[6];

  int B = in_sizes[0] / (3*WIDTH*WIDTH);
  int grid = B / CTAB;   // 4096/32 = 128 CTAs

  size_t smem = SMEM_FLOATS * sizeof(float);   // ~147 KB
  cudaFuncSetAttribute(pixelrnn_kernel,
                       cudaFuncAttributeMaxDynamicSharedMemorySize, (int)smem);

  pixelrnn_kernel<<<grid, NTHR, smem>>>(x, W_ih, W_hh, b_ih, b_hh, Wl, bl,
                                        (float*)d_out);
}

// round 15
// speedup vs baseline: 1.3666x; 1.0128x over previous
#include <cuda_runtime.h>

#define HID   64
#define RS    8
#define KIH   24
#define WIDTH 24
#define L0R   8
#define R0R   24
#define OW    16
#define WB    4          // batches per warp (warp fully owns them)
#define NWARP 8
#define NTHR  256
#define CTAB  32
#define NKP   44         // k-pairs (88 k)
#define RBW   25         // padded row stride in quads (bank stagger)

// smem float offsets
#define OFF_W    0
#define W_FLOATS (NKP*4*32*4)                // 22528
#define OFF_BIAS (OFF_W + W_FLOATS)          // 22528
#define OFF_WL   (OFF_BIAS + 256)            // 22784
#define OFF_BL   (OFF_WL + 192)              // 22976
#define OFF_HX   (OFF_BL + 4)                // 22980 (x4 -> 16B aligned)
#define HXBUF    (NWARP*WB*HID)              // 2048 per buffer
#define OFF_RBQ  (OFF_HX + 2*HXBUF)          // 27076
#define RBQ_FLOATS (NWARP*WB*3*RBW*4)        // 9600
#define SMEM_FLOATS (OFF_RBQ + RBQ_FLOATS)   // 36676 -> ~147 KB

typedef unsigned long long u64;

union F4U { float4 f4; struct { u64 lo, hi; } u; };

static __device__ __forceinline__ u64 pack2(float a, float b){
  u64 r; asm("mov.b64 %0, {%1, %2};" : "=l"(r) : "f"(a), "f"(b)); return r;
}
static __device__ __forceinline__ void unpack2(u64 v, float& a, float& b){
  asm("mov.b64 {%0, %1}, %2;" : "=f"(a), "=f"(b) : "l"(v));
}
static __device__ __forceinline__ u64 ffma2(u64 a, u64 b, u64 c){
  u64 d; asm("fma.rn.f32x2 %0, %1, %2, %3;" : "=l"(d) : "l"(a), "l"(b), "l"(c));
  return d;
}
static __device__ __forceinline__ float tanha(float x){
  float y; asm("tanh.approx.f32 %0, %1;" : "=f"(y) : "f"(x)); return y;
}
static __device__ __forceinline__ float sigf(float x){
  return fmaf(tanha(0.5f*x), 0.5f, 0.5f);
}

__global__ void __launch_bounds__(NTHR, 1)
pixelrnn_kernel(const float* __restrict__ x,
                const float* __restrict__ W_ih,
                const float* __restrict__ W_hh,
                const float* __restrict__ b_ih,
                const float* __restrict__ b_hh,
                const float* __restrict__ Wl,
                const float* __restrict__ bl,
                float* __restrict__ out)
{
  extern __shared__ float sm[];
  const int tid  = threadIdx.x;
  const int warp = tid >> 5, lane = tid & 31;

  // ---- stage weights (shared by all warps) ----
  // W4[(kp*4 + t)*32 + ln] = ( w(k0,rA), w(k0,rB), w(k1,rA), w(k1,rB) )
  //   k0 = 2kp, k1 = 2kp+1; rA = t*64 + ln, rB = rA + 32 (gate rows i,f,g,o)
  //   k < 24 -> W_ih col k; else W_hh col k-24
  //   u.lo = k0 pair (hidA,hidB); u.hi = k1 pair
  {
    float4* W4 = (float4*)(sm + OFF_W);
    for (int i = tid; i < NKP*4*32; i += NTHR){
      int ln = i & 31, t = (i >> 5) & 3, kp = i >> 7;
      int rA = t*64 + ln, rB = rA + 32;
      int k0 = 2*kp;
      float4 v;
      if (k0 < KIH){
        v = make_float4(W_ih[rA*KIH + k0],     W_ih[rB*KIH + k0],
                        W_ih[rA*KIH + k0 + 1], W_ih[rB*KIH + k0 + 1]);
      } else {
        int kk = k0 - KIH;
        v = make_float4(W_hh[rA*HID + kk],     W_hh[rB*HID + kk],
                        W_hh[rA*HID + kk + 1], W_hh[rB*HID + kk + 1]);
      }
      W4[i] = v;
    }
  }
  for (int i = tid; i < 256; i += NTHR) sm[OFF_BIAS + i] = b_ih[i] + b_hh[i];
  for (int i = tid; i < 3*HID; i += NTHR) sm[OFF_WL + i] = Wl[i];
  if (tid < 3) sm[OFF_BL + tid] = bl[tid];
  for (int i = tid; i < 2*HXBUF; i += NTHR) sm[OFF_HX + i] = 0.f;
  __syncthreads();

  const int bbase = blockIdx.x * CTAB + warp * WB;
  float* hxb0 = sm + OFF_HX + warp * (WB*HID);
  float* hxb1 = hxb0 + HXBUF;
  float4* rbq = (float4*)(sm + OFF_RBQ) + warp * (WB*3*RBW);
  float*  rbf = (float*)rbq;
  const float4* wq  = (const float4*)(sm + OFF_W) + lane;
  const float4* wlq = (const float4*)(sm + OFF_WL);

  // biases packed (hidA, hidB) per gate type
  u64 bj[4];
#pragma unroll
  for (int t = 0; t < 4; t++)
    bj[t] = pack2(sm[OFF_BIAS + t*64 + lane], sm[OFF_BIAS + t*64 + lane + 32]);

  float cx0[WB], cx1[WB];
#pragma unroll
  for (int b = 0; b < WB; b++){ cx0[b] = 0.f; cx1[b] = 0.f; }

  // v-head: 2 lanes per (vb,vch) dot; pid = lane>>1 in 0..11
  const int  pid = lane >> 1, sub = lane & 1;
  const int  vb = pid / 3, vch = pid - 3*vb;
  const bool vact = (lane < 24);
  const float blv = vact ? sm[OFF_BL + vch] : 0.f;
  float* outq = vact ? out + ((size_t)(bbase + vb)*3 + vch)*(OW*OW) : out;

  int ph = 0, sctr = 0;

  for (int r = L0R; r < R0R; r++){
    // init slots 0..7 from x (cols >= 8 get v-patched before any read)
    for (int i = lane; i < WB*3*8; i += 32){
      int b = i / 24;
      int rem = i - b*24;
      int ch = rem >> 3, s = rem & 7;
      const float* xr = x + (size_t)(bbase + b)*(3*WIDTH*WIDTH)
                          + ch*(WIDTH*WIDTH) + r*WIDTH + s;
      rbq[(b*3 + ch)*RBW + s] = make_float4(xr[0], xr[1], xr[2], xr[3]);
    }
    __syncwarp();

    for (int c = RS; c < WIDTH; c++){
      float* hxr = ph ? hxb1 : hxb0;   // h(t-1)
      float* hxw = ph ? hxb0 : hxb1;   // h(t)
      const float4* hxq = (const float4*)hxr;

      // acc[b][t] = (partial for hidA=lane, hidB=lane+32) of gate-type t
      u64 acc[WB][4];
#pragma unroll
      for (int b = 0; b < WB; b++)
#pragma unroll
        for (int t = 0; t < 4; t++) acc[b][t] = bj[t];

      // ---- input feed: 6 quads (iq -> ch=iq>>1, 4 k each, kp = 2iq, 2iq+1) ----
#pragma unroll
      for (int iq = 0; iq < 6; iq++){
        F4U wA0, wA1, wA2, wA3, wB0, wB1, wB2, wB3;
        wA0.f4 = wq[((2*iq+0)*4 + 0)*32];
        wA1.f4 = wq[((2*iq+0)*4 + 1)*32];
        wA2.f4 = wq[((2*iq+0)*4 + 2)*32];
        wA3.f4 = wq[((2*iq+0)*4 + 3)*32];
        wB0.f4 = wq[((2*iq+1)*4 + 0)*32];
        wB1.f4 = wq[((2*iq+1)*4 + 1)*32];
        wB2.f4 = wq[((2*iq+1)*4 + 2)*32];
        wB3.f4 = wq[((2*iq+1)*4 + 3)*32];
        int ch = iq >> 1;
        int base = c - RS + 4*(iq & 1);
#pragma unroll
        for (int b = 0; b < WB; b++){
          float4 a = rbq[(b*3 + ch)*RBW + base];
          u64 sx = pack2(a.x, a.x), sy = pack2(a.y, a.y);
          u64 sz = pack2(a.z, a.z), sw = pack2(a.w, a.w);
          acc[b][0] = ffma2(sx, wA0.u.lo, acc[b][0]);
          acc[b][1] = ffma2(sx, wA1.u.lo, acc[b][1]);
          acc[b][2] = ffma2(sx, wA2.u.lo, acc[b][2]);
          acc[b][3] = ffma2(sx, wA3.u.lo, acc[b][3]);
          acc[b][0] = ffma2(sy, wA0.u.hi, acc[b][0]);
          acc[b][1] = ffma2(sy, wA1.u.hi, acc[b][1]);
          acc[b][2] = ffma2(sy, wA2.u.hi, acc[b][2]);
          acc[b][3] = ffma2(sy, wA3.u.hi, acc[b][3]);
          acc[b][0] = ffma2(sz, wB0.u.lo, acc[b][0]);
          acc[b][1] = ffma2(sz, wB1.u.lo, acc[b][1]);
          acc[b][2] = ffma2(sz, wB2.u.lo, acc[b][2]);
          acc[b][3] = ffma2(sz, wB3.u.lo, acc[b][3]);
          acc[b][0] = ffma2(sw, wB0.u.hi, acc[b][0]);
          acc[b][1] = ffma2(sw, wB1.u.hi, acc[b][1]);
          acc[b][2] = ffma2(sw, wB2.u.hi, acc[b][2]);
          acc[b][3] = ffma2(sw, wB3.u.hi, acc[b][3]);
        }
      }

      // ---- hidden feed: 16 quads (jq -> kp = 12+2jq, 13+2jq) ----
#pragma unroll 8
      for (int jq = 0; jq < 16; jq++){
        F4U wA0, wA1, wA2, wA3, wB0, wB1, wB2, wB3;
        wA0.f4 = wq[((12 + 2*jq)*4 + 0)*32];
        wA1.f4 = wq[((12 + 2*jq)*4 + 1)*32];
        wA2.f4 = wq[((12 + 2*jq)*4 + 2)*32];
        wA3.f4 = wq[((12 + 2*jq)*4 + 3)*32];
        wB0.f4 = wq[((13 + 2*jq)*4 + 0)*32];
        wB1.f4 = wq[((13 + 2*jq)*4 + 1)*32];
        wB2.f4 = wq[((13 + 2*jq)*4 + 2)*32];
        wB3.f4 = wq[((13 + 2*jq)*4 + 3)*32];
#pragma unroll
        for (int b = 0; b < WB; b++){
          float4 a = hxq[b*16 + jq];
          u64 sx = pack2(a.x, a.x), sy = pack2(a.y, a.y);
          u64 sz = pack2(a.z, a.z), sw = pack2(a.w, a.w);
          acc[b][0] = ffma2(sx, wA0.u.lo, acc[b][0]);
          acc[b][1] = ffma2(sx, wA1.u.lo, acc[b][1]);
          acc[b][2] = ffma2(sx, wA2.u.lo, acc[b][2]);
          acc[b][3] = ffma2(sx, wA3.u.lo, acc[b][3]);
          acc[b][0] = ffma2(sy, wA0.u.hi, acc[b][0]);
          acc[b][1] = ffma2(sy, wA1.u.hi, acc[b][1]);
          acc[b][2] = ffma2(sy, wA2.u.hi, acc[b][2]);
          acc[b][3] = ffma2(sy, wA3.u.hi, acc[b][3]);
          acc[b][0] = ffma2(sz, wB0.u.lo, acc[b][0]);
          acc[b][1] = ffma2(sz, wB1.u.lo, acc[b][1]);
          acc[b][2] = ffma2(sz, wB2.u.lo, acc[b][2]);
          acc[b][3] = ffma2(sz, wB3.u.lo, acc[b][3]);
          acc[b][0] = ffma2(sw, wB0.u.hi, acc[b][0]);
          acc[b][1] = ffma2(sw, wB1.u.hi, acc[b][1]);
          acc[b][2] = ffma2(sw, wB2.u.hi, acc[b][2]);
          acc[b][3] = ffma2(sw, wB3.u.hi, acc[b][3]);
        }
      }

      // ---- lane-local cell update (gates already fully summed per half) ----
#pragma unroll
      for (int b = 0; b < WB; b++){
        float giA, giB, gfA, gfB, ggA, ggB, goA, goB;
        unpack2(acc[b][0], giA, giB);
        unpack2(acc[b][1], gfA, gfB);
        unpack2(acc[b][2], ggA, ggB);
        unpack2(acc[b][3], goA, goB);
        float c0 = sigf(gfA)*cx0[b] + sigf(giA)*tanha(ggA);
        float c1 = sigf(gfB)*cx1[b] + sigf(giB)*tanha(ggB);
        cx0[b] = c0; cx1[b] = c1;
        hxw[b*HID + lane]      = sigf(goA)*tanha(c0);
        hxw[b*HID + lane + 32] = sigf(goB)*tanha(c1);
      }
      __syncwarp();

      // ---- head v: 2 lanes per dot (lanes 0..23), shfl-combine ----
      float vtot = 0.f;
      if (vact){
        const float4* hq = (const float4*)hxw;
        u64 va = pack2(0.f, 0.f);
#pragma unroll
        for (int j = 0; j < 8; j++){
          F4U a; a.f4 = hq[vb*16 + sub*8 + j];
          F4U w; w.f4 = wlq[vch*16 + sub*8 + j];
          va = ffma2(a.u.lo, w.u.lo, va);
          va = ffma2(a.u.hi, w.u.hi, va);
        }
        float v0, v1; unpack2(va, v0, v1);
        vtot = v0 + v1;
      }
      vtot += __shfl_xor_sync(0xFFFFFFFFu, vtot, 1);
      if (vact && sub == 0){
        float v = vtot + blv;
        v = fmaxf(v, 0.01f*v);
#pragma unroll
        for (int t = 0; t < 4; t++)
          rbf[((vb*3 + vch)*RBW + (c - t))*4 + t] = v;
        outq[sctr] = v;
      }
      __syncwarp();
      ph ^= 1;
      sctr++;
    }
  }
}

extern "C" void kernel_launch(void* const* d_in, const int* in_sizes, int n_in,
                              void* d_out, int out_size)
{
  const float* x    = (const float*)d_in[0];
  const float* W_ih = (const float*)d_in[1];
  const float* W_hh = (const float*)d_in[2];
  const float* b_ih = (const float*)d_in[3];
  const float* b_hh = (const float*)d_in[4];
  const float* Wl   = (const float*)d_in[5];
  const float* bl   = (const float*)d_in[6];

  int B = in_sizes[0] / (3*WIDTH*WIDTH);
  int grid = B / CTAB;   // 4096/32 = 128 CTAs

  size_t smem = SMEM_FLOATS * sizeof(float);   // ~147 KB
  cudaFuncSetAttribute(pixelrnn_kernel,
                       cudaFuncAttributeMaxDynamicSharedMemorySize, (int)smem);

  pixelrnn_kernel<<<grid, NTHR, smem>>>(x, W_ih, W_hh, b_ih, b_hh, Wl, bl,
                                        (float*)d_out);
}

// round 16
// speedup vs baseline: 1.4705x; 1.0761x over previous
#include <cuda_runtime.h>

#define HID   64
#define RS    8
#define KIH   24
#define WIDTH 24
#define L0R   8
#define R0R   24
#define OW    16
#define WB    4          // batches per warp (warp fully owns them)
#define NWARP 8
#define NTHR  256
#define CTAB  32
#define NKP   44         // k-pairs (88 k)
#define RBW   24

// smem float offsets
#define OFF_W    0
#define W_FLOATS (NKP*4*32*4)                // 22528
#define OFF_BIAS (OFF_W + W_FLOATS)          // 22528
#define OFF_WL   (OFF_BIAS + 256)            // 22784
#define OFF_BL   (OFF_WL + 192)              // 22976
#define OFF_HX   (OFF_BL + 4)                // 22980 (x4 -> 16B aligned)
#define HXBUF    (NWARP*WB*HID)              // 2048 per buffer
#define OFF_RBQ  (OFF_HX + 2*HXBUF)          // 27076
#define RBQ_FLOATS (NWARP*WB*3*RBW*4)        // 9216
#define SMEM_FLOATS (OFF_RBQ + RBQ_FLOATS)   // 36292 -> ~145 KB

typedef unsigned long long u64;

union F4U { float4 f4; struct { u64 lo, hi; } u; };

static __device__ __forceinline__ u64 pack2(float a, float b){
  u64 r; asm("mov.b64 %0, {%1, %2};" : "=l"(r) : "f"(a), "f"(b)); return r;
}
static __device__ __forceinline__ void unpack2(u64 v, float& a, float& b){
  asm("mov.b64 {%0, %1}, %2;" : "=f"(a), "=f"(b) : "l"(v));
}
static __device__ __forceinline__ u64 ffma2(u64 a, u64 b, u64 c){
  u64 d; asm("fma.rn.f32x2 %0, %1, %2, %3;" : "=l"(d) : "l"(a), "l"(b), "l"(c));
  return d;
}
static __device__ __forceinline__ float tanha(float x){
  float y; asm("tanh.approx.f32 %0, %1;" : "=f"(y) : "f"(x)); return y;
}
static __device__ __forceinline__ float sigf(float x){
  return fmaf(tanha(0.5f*x), 0.5f, 0.5f);
}

__global__ void __launch_bounds__(NTHR, 1)
pixelrnn_kernel(const float* __restrict__ x,
                const float* __restrict__ W_ih,
                const float* __restrict__ W_hh,
                const float* __restrict__ b_ih,
                const float* __restrict__ b_hh,
                const float* __restrict__ Wl,
                const float* __restrict__ bl,
                float* __restrict__ out)
{
  extern __shared__ float sm[];
  const int tid  = threadIdx.x;
  const int warp = tid >> 5, lane = tid & 31;

  // ---- stage weights (shared by all warps) ----
  // W4[(kp*4 + t)*32 + ln] = ( w(k0,rA), w(k0,rB), w(k1,rA), w(k1,rB) )
  //   k0 = 2kp, k1 = 2kp+1; rA = t*64 + ln, rB = rA + 32 (gate rows i,f,g,o)
  //   k < 24 -> W_ih col k; else W_hh col k-24
  //   u.lo = k0 pair (hidA,hidB); u.hi = k1 pair
  {
    float4* W4 = (float4*)(sm + OFF_W);
    for (int i = tid; i < NKP*4*32; i += NTHR){
      int ln = i & 31, t = (i >> 5) & 3, kp = i >> 7;
      int rA = t*64 + ln, rB = rA + 32;
      int k0 = 2*kp;
      float4 v;
      if (k0 < KIH){
        v = make_float4(W_ih[rA*KIH + k0],     W_ih[rB*KIH + k0],
                        W_ih[rA*KIH + k0 + 1], W_ih[rB*KIH + k0 + 1]);
      } else {
        int kk = k0 - KIH;
        v = make_float4(W_hh[rA*HID + kk],     W_hh[rB*HID + kk],
                        W_hh[rA*HID + kk + 1], W_hh[rB*HID + kk + 1]);
      }
      W4[i] = v;
    }
  }
  for (int i = tid; i < 256; i += NTHR) sm[OFF_BIAS + i] = b_ih[i] + b_hh[i];
  for (int i = tid; i < 3*HID; i += NTHR) sm[OFF_WL + i] = Wl[i];
  if (tid < 3) sm[OFF_BL + tid] = bl[tid];
  for (int i = tid; i < 2*HXBUF; i += NTHR) sm[OFF_HX + i] = 0.f;
  __syncthreads();

  const int bbase = blockIdx.x * CTAB + warp * WB;
  float* hxb0 = sm + OFF_HX + warp * (WB*HID);
  float* hxb1 = hxb0 + HXBUF;
  float4* rbq = (float4*)(sm + OFF_RBQ) + warp * (WB*3*RBW);
  float*  rbf = (float*)rbq;
  const float4* wq  = (const float4*)(sm + OFF_W) + lane;
  const float4* wlq = (const float4*)(sm + OFF_WL);

  // biases packed (hidA, hidB) per gate type
  u64 bj[4];
#pragma unroll
  for (int t = 0; t < 4; t++)
    bj[t] = pack2(sm[OFF_BIAS + t*64 + lane], sm[OFF_BIAS + t*64 + lane + 32]);

  float cx0[WB], cx1[WB];
#pragma unroll
  for (int b = 0; b < WB; b++){ cx0[b] = 0.f; cx1[b] = 0.f; }

  const int  vb = lane / 3, vch = lane - 3*vb;     // lanes 0..11 own (vb,vch)
  const bool vact = (lane < 3*WB);
  const float blv = vact ? sm[OFF_BL + vch] : 0.f;
  float* outq = vact ? out + ((size_t)(bbase + vb)*3 + vch)*(OW*OW) : out;

  int ph = 0, sctr = 0;

  for (int r = L0R; r < R0R; r++){
    // init slots 0..7 from x (cols >= 8 get v-patched before any read)
    for (int i = lane; i < WB*3*8; i += 32){
      int b = i / 24;
      int rem = i - b*24;
      int ch = rem >> 3, s = rem & 7;
      const float* xr = x + (size_t)(bbase + b)*(3*WIDTH*WIDTH)
                          + ch*(WIDTH*WIDTH) + r*WIDTH + s;
      rbq[(b*3 + ch)*RBW + s] = make_float4(xr[0], xr[1], xr[2], xr[3]);
    }
    __syncwarp();

    for (int c = RS; c < WIDTH; c++){
      float* hxr = ph ? hxb1 : hxb0;   // h(t-1)
      float* hxw = ph ? hxb0 : hxb1;   // h(t)
      const float4* hxq = (const float4*)hxr;

      // acc[b][t] = (partial for hidA=lane, hidB=lane+32) of gate-type t
      u64 acc[WB][4];
#pragma unroll
      for (int b = 0; b < WB; b++)
#pragma unroll
        for (int t = 0; t < 4; t++) acc[b][t] = bj[t];

      // ---- input feed: 6 quads (iq -> ch=iq>>1, 4 k each, kp = 2iq, 2iq+1) ----
#pragma unroll
      for (int iq = 0; iq < 6; iq++){
        F4U wA0, wA1, wA2, wA3, wB0, wB1, wB2, wB3;
        wA0.f4 = wq[((2*iq+0)*4 + 0)*32];
        wA1.f4 = wq[((2*iq+0)*4 + 1)*32];
        wA2.f4 = wq[((2*iq+0)*4 + 2)*32];
        wA3.f4 = wq[((2*iq+0)*4 + 3)*32];
        wB0.f4 = wq[((2*iq+1)*4 + 0)*32];
        wB1.f4 = wq[((2*iq+1)*4 + 1)*32];
        wB2.f4 = wq[((2*iq+1)*4 + 2)*32];
        wB3.f4 = wq[((2*iq+1)*4 + 3)*32];
        int ch = iq >> 1;
        int base = c - RS + 4*(iq & 1);
#pragma unroll
        for (int b = 0; b < WB; b++){
          float4 a = rbq[(b*3 + ch)*RBW + base];
          u64 sx = pack2(a.x, a.x), sy = pack2(a.y, a.y);
          u64 sz = pack2(a.z, a.z), sw = pack2(a.w, a.w);
          acc[b][0] = ffma2(sx, wA0.u.lo, acc[b][0]);
          acc[b][1] = ffma2(sx, wA1.u.lo, acc[b][1]);
          acc[b][2] = ffma2(sx, wA2.u.lo, acc[b][2]);
          acc[b][3] = ffma2(sx, wA3.u.lo, acc[b][3]);
          acc[b][0] = ffma2(sy, wA0.u.hi, acc[b][0]);
          acc[b][1] = ffma2(sy, wA1.u.hi, acc[b][1]);
          acc[b][2] = ffma2(sy, wA2.u.hi, acc[b][2]);
          acc[b][3] = ffma2(sy, wA3.u.hi, acc[b][3]);
          acc[b][0] = ffma2(sz, wB0.u.lo, acc[b][0]);
          acc[b][1] = ffma2(sz, wB1.u.lo, acc[b][1]);
          acc[b][2] = ffma2(sz, wB2.u.lo, acc[b][2]);
          acc[b][3] = ffma2(sz, wB3.u.lo, acc[b][3]);
          acc[b][0] = ffma2(sw, wB0.u.hi, acc[b][0]);
          acc[b][1] = ffma2(sw, wB1.u.hi, acc[b][1]);
          acc[b][2] = ffma2(sw, wB2.u.hi, acc[b][2]);
          acc[b][3] = ffma2(sw, wB3.u.hi, acc[b][3]);
        }
      }

      // ---- hidden feed: 16 quads (jq -> kp = 12+2jq, 13+2jq) ----
#pragma unroll 8
      for (int jq = 0; jq < 16; jq++){
        F4U wA0, wA1, wA2, wA3, wB0, wB1, wB2, wB3;
        wA0.f4 = wq[((12 + 2*jq)*4 + 0)*32];
        wA1.f4 = wq[((12 + 2*jq)*4 + 1)*32];
        wA2.f4 = wq[((12 + 2*jq)*4 + 2)*32];
        wA3.f4 = wq[((12 + 2*jq)*4 + 3)*32];
        wB0.f4 = wq[((13 + 2*jq)*4 + 0)*32];
        wB1.f4 = wq[((13 + 2*jq)*4 + 1)*32];
        wB2.f4 = wq[((13 + 2*jq)*4 + 2)*32];
        wB3.f4 = wq[((13 + 2*jq)*4 + 3)*32];
#pragma unroll
        for (int b = 0; b < WB; b++){
          float4 a = hxq[b*16 + jq];
          u64 sx = pack2(a.x, a.x), sy = pack2(a.y, a.y);
          u64 sz = pack2(a.z, a.z), sw = pack2(a.w, a.w);
          acc[b][0] = ffma2(sx, wA0.u.lo, acc[b][0]);
          acc[b][1] = ffma2(sx, wA1.u.lo, acc[b][1]);
          acc[b][2] = ffma2(sx, wA2.u.lo, acc[b][2]);
          acc[b][3] = ffma2(sx, wA3.u.lo, acc[b][3]);
          acc[b][0] = ffma2(sy, wA0.u.hi, acc[b][0]);
          acc[b][1] = ffma2(sy, wA1.u.hi, acc[b][1]);
          acc[b][2] = ffma2(sy, wA2.u.hi, acc[b][2]);
          acc[b][3] = ffma2(sy, wA3.u.hi, acc[b][3]);
          acc[b][0] = ffma2(sz, wB0.u.lo, acc[b][0]);
          acc[b][1] = ffma2(sz, wB1.u.lo, acc[b][1]);
          acc[b][2] = ffma2(sz, wB2.u.lo, acc[b][2]);
          acc[b][3] = ffma2(sz, wB3.u.lo, acc[b][3]);
          acc[b][0] = ffma2(sw, wB0.u.hi, acc[b][0]);
          acc[b][1] = ffma2(sw, wB1.u.hi, acc[b][1]);
          acc[b][2] = ffma2(sw, wB2.u.hi, acc[b][2]);
          acc[b][3] = ffma2(sw, wB3.u.hi, acc[b][3]);
        }
      }

      // ---- lane-local cell update (gates already fully summed per half) ----
#pragma unroll
      for (int b = 0; b < WB; b++){
        float giA, giB, gfA, gfB, ggA, ggB, goA, goB;
        unpack2(acc[b][0], giA, giB);
        unpack2(acc[b][1], gfA, gfB);
        unpack2(acc[b][2], ggA, ggB);
        unpack2(acc[b][3], goA, goB);
        float c0 = sigf(gfA)*cx0[b] + sigf(giA)*tanha(ggA);
        float c1 = sigf(gfB)*cx1[b] + sigf(giB)*tanha(ggB);
        cx0[b] = c0; cx1[b] = c1;
        hxw[b*HID + lane]      = sigf(goA)*tanha(c0);
        hxw[b*HID + lane + 32] = sigf(goB)*tanha(c1);
      }
      __syncwarp();

      // ---- head v (lanes 0..11: batch vb, channel vch) ----
      if (vact){
        const float4* hq = (const float4*)hxw;
        u64 va = pack2(0.f, 0.f);
#pragma unroll
        for (int j = 0; j < 16; j++){
          F4U a; a.f4 = hq[vb*16 + j];
          F4U w; w.f4 = wlq[vch*16 + j];
          va = ffma2(a.u.lo, w.u.lo, va);
          va = ffma2(a.u.hi, w.u.hi, va);
        }
        float v0, v1; unpack2(va, v0, v1);
        float v = v0 + v1 + blv;
        v = fmaxf(v, 0.01f*v);
#pragma unroll
        for (int t = 0; t < 4; t++)
          rbf[((vb*3 + vch)*RBW + (c - t))*4 + t] = v;
        outq[sctr] = v;
      }
      __syncwarp();
      ph ^= 1;
      sctr++;
    }
  }
}

extern "C" void kernel_launch(void* const* d_in, const int* in_sizes, int n_in,
                              void* d_out, int out_size)
{
  const float* x    = (const float*)d_in[0];
  const float* W_ih = (const float*)d_in[1];
  const float* W_hh = (const float*)d_in[2];
  const float* b_ih = (const float*)d_in[3];
  const float* b_hh = (const float*)d_in[4];
  const float* Wl   = (const float*)d_in[5];
  const float* bl   = (const float*)d_in[6];

  int B = in_sizes[0] / (3*WIDTH*WIDTH);
  int grid = B / CTAB;   // 4096/32 = 128 CTAs

  size_t smem = SMEM_FLOATS * sizeof(float);   // ~145 KB
  cudaFuncSetAttribute(pixelrnn_kernel,
                       cudaFuncAttributeMaxDynamicSharedMemorySize, (int)smem);

  pixelrnn_kernel<<<grid, NTHR, smem>>>(x, W_ih, W_hh, b_ih, b_hh, Wl, bl,
                                        (float*)d_out);
}

// round 17
// speedup vs baseline: 1.4908x; 1.0138x over previous
#include <cuda_runtime.h>

#define HID   64
#define RS    8
#define KIH   24
#define WIDTH 24
#define L0R   8
#define R0R   24
#define OW    16
#define WB    4          // batches per warp (warp fully owns them)
#define NWARP 8
#define NTHR  256
#define CTAB  32
#define NKP   44         // k-pairs (88 k)
#define RBW   24

// smem float offsets
#define OFF_W    0
#define W_FLOATS (NKP*4*32*4)                // 22528
#define OFF_BIAS (OFF_W + W_FLOATS)          // 22528
#define OFF_WL   (OFF_BIAS + 256)            // 22784
#define OFF_BL   (OFF_WL + 192)              // 22976
#define OFF_HX   (OFF_BL + 4)                // 22980 (x4 -> 16B aligned)
#define HXBUF    (NWARP*WB*HID)              // 2048 per buffer
#define OFF_RBQ  (OFF_HX + 2*HXBUF)          // 27076
#define RBQ_FLOATS (NWARP*WB*3*RBW*4)        // 9216
#define SMEM_FLOATS (OFF_RBQ + RBQ_FLOATS)   // 36292 -> ~145 KB

typedef unsigned long long u64;

union F4U { float4 f4; struct { u64 lo, hi; } u; };

static __device__ __forceinline__ u64 pack2(float a, float b){
  u64 r; asm("mov.b64 %0, {%1, %2};" : "=l"(r) : "f"(a), "f"(b)); return r;
}
static __device__ __forceinline__ void unpack2(u64 v, float& a, float& b){
  asm("mov.b64 {%0, %1}, %2;" : "=f"(a), "=f"(b) : "l"(v));
}
static __device__ __forceinline__ u64 ffma2(u64 a, u64 b, u64 c){
  u64 d; asm("fma.rn.f32x2 %0, %1, %2, %3;" : "=l"(d) : "l"(a), "l"(b), "l"(c));
  return d;
}
static __device__ __forceinline__ float tanha(float x){
  float y; asm("tanh.approx.f32 %0, %1;" : "=f"(y) : "f"(x)); return y;
}
static __device__ __forceinline__ float sigf(float x){
  return fmaf(tanha(0.5f*x), 0.5f, 0.5f);
}

__global__ void __launch_bounds__(NTHR, 1)
pixelrnn_kernel(const float* __restrict__ x,
                const float* __restrict__ W_ih,
                const float* __restrict__ W_hh,
                const float* __restrict__ b_ih,
                const float* __restrict__ b_hh,
                const float* __restrict__ Wl,
                const float* __restrict__ bl,
                float* __restrict__ out)
{
  extern __shared__ float sm[];
  const int tid  = threadIdx.x;
  const int warp = tid >> 5, lane = tid & 31;

  // ---- stage weights (shared by all warps) ----
  // W4[(kp*4 + t)*32 + ln] = ( w(k0,rA), w(k0,rB), w(k1,rA), w(k1,rB) )
  //   k0 = 2kp, k1 = 2kp+1; rA = t*64 + ln, rB = rA + 32 (gate rows i,f,g,o)
  //   k < 24 -> W_ih col k; else W_hh col k-24
  //   u.lo = k0 pair (hidA,hidB); u.hi = k1 pair
  {
    float4* W4 = (float4*)(sm + OFF_W);
    for (int i = tid; i < NKP*4*32; i += NTHR){
      int ln = i & 31, t = (i >> 5) & 3, kp = i >> 7;
      int rA = t*64 + ln, rB = rA + 32;
      int k0 = 2*kp;
      float4 v;
      if (k0 < KIH){
        v = make_float4(W_ih[rA*KIH + k0],     W_ih[rB*KIH + k0],
                        W_ih[rA*KIH + k0 + 1], W_ih[rB*KIH + k0 + 1]);
      } else {
        int kk = k0 - KIH;
        v = make_float4(W_hh[rA*HID + kk],     W_hh[rB*HID + kk],
                        W_hh[rA*HID + kk + 1], W_hh[rB*HID + kk + 1]);
      }
      W4[i] = v;
    }
  }
  for (int i = tid; i < 256; i += NTHR) sm[OFF_BIAS + i] = b_ih[i] + b_hh[i];
  for (int i = tid; i < 3*HID; i += NTHR) sm[OFF_WL + i] = Wl[i];
  if (tid < 3) sm[OFF_BL + tid] = bl[tid];
  for (int i = tid; i < 2*HXBUF; i += NTHR) sm[OFF_HX + i] = 0.f;
  __syncthreads();

  const int bbase = blockIdx.x * CTAB + warp * WB;
  float* hxb0 = sm + OFF_HX + warp * (WB*HID);
  float* hxb1 = hxb0 + HXBUF;
  float4* rbq = (float4*)(sm + OFF_RBQ) + warp * (WB*3*RBW);
  float*  rbf = (float*)rbq;
  const float4* wq  = (const float4*)(sm + OFF_W) + lane;
  const float4* wlq = (const float4*)(sm + OFF_WL);

  // biases packed (hidA, hidB) per gate type
  u64 bj[4];
#pragma unroll
  for (int t = 0; t < 4; t++)
    bj[t] = pack2(sm[OFF_BIAS + t*64 + lane], sm[OFF_BIAS + t*64 + lane + 32]);

  float cx0[WB], cx1[WB];
#pragma unroll
  for (int b = 0; b < WB; b++){ cx0[b] = 0.f; cx1[b] = 0.f; }

  const int  vb = lane / 3, vch = lane - 3*vb;     // lanes 0..11 own (vb,vch)
  const bool vact = (lane < 3*WB);
  const float blv = vact ? sm[OFF_BL + vch] : 0.f;
  float* outq = vact ? out + ((size_t)(bbase + vb)*3 + vch)*(OW*OW) : out;

  int ph = 0, sctr = 0;

  for (int r = L0R; r < R0R; r++){
    // init slots 0..7 from x (cols >= 8 get v-patched before any read)
    for (int i = lane; i < WB*3*8; i += 32){
      int b = i / 24;
      int rem = i - b*24;
      int ch = rem >> 3, s = rem & 7;
      const float* xr = x + (size_t)(bbase + b)*(3*WIDTH*WIDTH)
                          + ch*(WIDTH*WIDTH) + r*WIDTH + s;
      rbq[(b*3 + ch)*RBW + s] = make_float4(xr[0], xr[1], xr[2], xr[3]);
    }
    __syncwarp();

    for (int c = RS; c < WIDTH; c++){
      float* hxr = ph ? hxb1 : hxb0;   // h(t-1)
      float* hxw = ph ? hxb0 : hxb1;   // h(t)
      const float4* hxq = (const float4*)hxr;

      // acc[b][t] = (partial for hidA=lane, hidB=lane+32) of gate-type t
      u64 acc[WB][4];
#pragma unroll
      for (int b = 0; b < WB; b++)
#pragma unroll
        for (int t = 0; t < 4; t++) acc[b][t] = bj[t];

      // double-buffered weight quads: 8 per iteration (kpA:t0..3, kpB:t0..3)
      F4U wbuf[2][8];
#pragma unroll
      for (int t = 0; t < 4; t++){
        wbuf[0][t].f4     = wq[((0)*4 + t)*32];   // kp=0
        wbuf[0][4 + t].f4 = wq[((1)*4 + t)*32];   // kp=1
      }

      // ---- input feed: 6 quads (iq -> ch=iq>>1, kp = 2iq, 2iq+1) ----
#pragma unroll
      for (int iq = 0; iq < 6; iq++){
        const int cur = iq & 1, nxt = cur ^ 1;
        // prefetch next iteration's weights (iq=5 prefetches hidden jq=0)
        const int kpA = (iq < 5) ? 2*(iq + 1) : 12;
#pragma unroll
        for (int t = 0; t < 4; t++){
          wbuf[nxt][t].f4     = wq[((kpA)*4 + t)*32];
          wbuf[nxt][4 + t].f4 = wq[((kpA + 1)*4 + t)*32];
        }
        int ch = iq >> 1;
        int base = c - RS + 4*(iq & 1);
#pragma unroll
        for (int b = 0; b < WB; b++){
          float4 a = rbq[(b*3 + ch)*RBW + base];
          u64 sx = pack2(a.x, a.x), sy = pack2(a.y, a.y);
          u64 sz = pack2(a.z, a.z), sw = pack2(a.w, a.w);
          acc[b][0] = ffma2(sx, wbuf[cur][0].u.lo, acc[b][0]);
          acc[b][1] = ffma2(sx, wbuf[cur][1].u.lo, acc[b][1]);
          acc[b][2] = ffma2(sx, wbuf[cur][2].u.lo, acc[b][2]);
          acc[b][3] = ffma2(sx, wbuf[cur][3].u.lo, acc[b][3]);
          acc[b][0] = ffma2(sy, wbuf[cur][0].u.hi, acc[b][0]);
          acc[b][1] = ffma2(sy, wbuf[cur][1].u.hi, acc[b][1]);
          acc[b][2] = ffma2(sy, wbuf[cur][2].u.hi, acc[b][2]);
          acc[b][3] = ffma2(sy, wbuf[cur][3].u.hi, acc[b][3]);
          acc[b][0] = ffma2(sz, wbuf[cur][4].u.lo, acc[b][0]);
          acc[b][1] = ffma2(sz, wbuf[cur][5].u.lo, acc[b][1]);
          acc[b][2] = ffma2(sz, wbuf[cur][6].u.lo, acc[b][2]);
          acc[b][3] = ffma2(sz, wbuf[cur][7].u.lo, acc[b][3]);
          acc[b][0] = ffma2(sw, wbuf[cur][4].u.hi, acc[b][0]);
          acc[b][1] = ffma2(sw, wbuf[cur][5].u.hi, acc[b][1]);
          acc[b][2] = ffma2(sw, wbuf[cur][6].u.hi, acc[b][2]);
          acc[b][3] = ffma2(sw, wbuf[cur][7].u.hi, acc[b][3]);
        }
      }

      // ---- hidden feed: 16 quad-iters (jq -> kp = 12+2jq, 13+2jq) ----
      // after input loop (iq=5 had cur=1), jq=0 weights sit in wbuf[0]
#pragma unroll
      for (int jq = 0; jq < 16; jq++){
        const int cur = jq & 1, nxt = cur ^ 1;
        if (jq < 15){
          const int kpA = 14 + 2*jq;
#pragma unroll
          for (int t = 0; t < 4; t++){
            wbuf[nxt][t].f4     = wq[((kpA)*4 + t)*32];
            wbuf[nxt][4 + t].f4 = wq[((kpA + 1)*4 + t)*32];
          }
        }
#pragma unroll
        for (int b = 0; b < WB; b++){
          float4 a = hxq[b*16 + jq];
          u64 sx = pack2(a.x, a.x), sy = pack2(a.y, a.y);
          u64 sz = pack2(a.z, a.z), sw = pack2(a.w, a.w);
          acc[b][0] = ffma2(sx, wbuf[cur][0].u.lo, acc[b][0]);
          acc[b][1] = ffma2(sx, wbuf[cur][1].u.lo, acc[b][1]);
          acc[b][2] = ffma2(sx, wbuf[cur][2].u.lo, acc[b][2]);
          acc[b][3] = ffma2(sx, wbuf[cur][3].u.lo, acc[b][3]);
          acc[b][0] = ffma2(sy, wbuf[cur][0].u.hi, acc[b][0]);
          acc[b][1] = ffma2(sy, wbuf[cur][1].u.hi, acc[b][1]);
          acc[b][2] = ffma2(sy, wbuf[cur][2].u.hi, acc[b][2]);
          acc[b][3] = ffma2(sy, wbuf[cur][3].u.hi, acc[b][3]);
          acc[b][0] = ffma2(sz, wbuf[cur][4].u.lo, acc[b][0]);
          acc[b][1] = ffma2(sz, wbuf[cur][5].u.lo, acc[b][1]);
          acc[b][2] = ffma2(sz, wbuf[cur][6].u.lo, acc[b][2]);
          acc[b][3] = ffma2(sz, wbuf[cur][7].u.lo, acc[b][3]);
          acc[b][0] = ffma2(sw, wbuf[cur][4].u.hi, acc[b][0]);
          acc[b][1] = ffma2(sw, wbuf[cur][5].u.hi, acc[b][1]);
          acc[b][2] = ffma2(sw, wbuf[cur][6].u.hi, acc[b][2]);
          acc[b][3] = ffma2(sw, wbuf[cur][7].u.hi, acc[b][3]);
        }
      }

      // ---- lane-local cell update (gates already fully summed per half) ----
#pragma unroll
      for (int b = 0; b < WB; b++){
        float giA, giB, gfA, gfB, ggA, ggB, goA, goB;
        unpack2(acc[b][0], giA, giB);
        unpack2(acc[b][1], gfA, gfB);
        unpack2(acc[b][2], ggA, ggB);
        unpack2(acc[b][3], goA, goB);
        float c0 = sigf(gfA)*cx0[b] + sigf(giA)*tanha(ggA);
        float c1 = sigf(gfB)*cx1[b] + sigf(giB)*tanha(ggB);
        cx0[b] = c0; cx1[b] = c1;
        hxw[b*HID + lane]      = sigf(goA)*tanha(c0);
        hxw[b*HID + lane + 32] = sigf(goB)*tanha(c1);
      }
      __syncwarp();

      // ---- head v (lanes 0..11: batch vb, channel vch) ----
      if (vact){
        const float4* hq = (const float4*)hxw;
        u64 va = pack2(0.f, 0.f);
#pragma unroll
        for (int j = 0; j < 16; j++){
          F4U a; a.f4 = hq[vb*16 + j];
          F4U w; w.f4 = wlq[vch*16 + j];
          va = ffma2(a.u.lo, w.u.lo, va);
          va = ffma2(a.u.hi, w.u.hi, va);
        }
        float v0, v1; unpack2(va, v0, v1);
        float v = v0 + v1 + blv;
        v = fmaxf(v, 0.01f*v);
#pragma unroll
        for (int t = 0; t < 4; t++)
          rbf[((vb*3 + vch)*RBW + (c - t))*4 + t] = v;
        outq[sctr] = v;
      }
      __syncwarp();
      ph ^= 1;
      sctr++;
    }
  }
}

extern "C" void kernel_launch(void* const* d_in, const int* in_sizes, int n_in,
                              void* d_out, int out_size)
{
  const float* x    = (const float*)d_in[0];
  const float* W_ih = (const float*)d_in[1];
  const float* W_hh = (const float*)d_in[2];
  const float* b_ih = (const float*)d_in[3];
  const float* b_hh = (const float*)d_in[4];
  const float* Wl   = (const float*)d_in[5];
  const float* bl   = (const float*)d_in[6];

  int B = in_sizes[0] / (3*WIDTH*WIDTH);
  int grid = B / CTAB;   // 4096/32 = 128 CTAs

  size_t smem = SMEM_FLOATS * sizeof(float);   // ~145 KB
  cudaFuncSetAttribute(pixelrnn_kernel,
                       cudaFuncAttributeMaxDynamicSharedMemorySize, (int)smem);

  pixelrnn_kernel<<<grid, NTHR, smem>>>(x, W_ih, W_hh, b_ih, b_hh, Wl, bl,
                                        (float*)d_out);
}